// round 11
// baseline (speedup 1.0000x reference)
#include <cuda_runtime.h>
#include <cuda_bf16.h>
#include <cstdint>

// DeterministicLattice: ring-stencil fusion + 5 nonlinear outputs.
// R11 (= R8..R10 resubmit after broker timeouts):
//     R7 structure (1 float4/thread, 32 regs, occ~79%, 122.9us measured)
//     + SINGLE change: __stwt (write-through, no L2 allocate) on the 5 output
//     stores, replacing __stcs.
// History: R1 plain 125.2us (DRAM 77.5%); R6 2x-unroll 167.6us (FALSIFIED:
//     occ drop + stride-2 uncoalesced); R7 __stcs 122.9us (DRAM 78.7%).
//
// N=65536 rows (power of two -> ring via & mask), D=512 cols.
// Mandatory DRAM traffic: 128MB in + 640MB out = 768MB. Floor @8TB/s = 96us.

#define NODES      65536
#define DIMV       512
#define V4_PER_ROW (DIMV / 4)            // 128
#define TOTAL_V4   (NODES * V4_PER_ROW)  // 8388608
#define OUT_STRIDE_V4 TOTAL_V4           // one full output plane, in float4 units

__device__ __forceinline__ float tanh_ap(float x) {
    float y;
    asm("tanh.approx.f32 %0, %1;" : "=f"(y) : "f"(x));
    return y;
}

__global__ __launch_bounds__(256)
void lattice_kernel(const float4* __restrict__ x, float4* __restrict__ out) {
    const float PHI      = 1.6180339887498949f;
    const float INV_PHI  = 0.6180339887498949f;   // 1/PHI
    const float INV_DEN  = 0.27639320225002106f;  // 1/(PHI+2)
    const float HALF_PHI = 0.80901699437494745f;  // PHI/2

    int idx = blockIdx.x * blockDim.x + threadIdx.x;   // [0, TOTAL_V4)
    int row = idx >> 7;           // idx / 128
    int col = idx & (V4_PER_ROW - 1);
    int up  = ((row - 1) & (NODES - 1)) * V4_PER_ROW + col;  // roll +1
    int dn  = ((row + 1) & (NODES - 1)) * V4_PER_ROW + col;  // roll -1

    float4 xc = __ldg(&x[idx]);
    float4 xl = __ldg(&x[up]);
    float4 xr = __ldg(&x[dn]);

    float4 o0, o1, o2, o3, o4;

    #pragma unroll
    for (int k = 0; k < 4; k++) {
        float c = (&xc.x)[k];
        float l = (&xl.x)[k];
        float r = (&xr.x)[k];

        float f = (PHI * c + l + r) * INV_DEN;

        float t      = tanh_ap(f);
        float bloom  = tanh_ap(PHI * f);
        float crown  = 0.5f + 0.5f * tanh_ap(HALF_PHI * f);  // sigmoid(PHI*f)
        float triad  = __sinf(f) * __cosf(PHI * f);
        float spiral = f * __expf(-fabsf(f) * INV_PHI);
        float ident  = f + INV_PHI * t;

        (&o0.x)[k] = ident;
        (&o1.x)[k] = bloom;
        (&o2.x)[k] = crown;
        (&o3.x)[k] = triad;
        (&o4.x)[k] = spiral;
    }

    // Write-through stores: no L2 allocation for the 640MB one-shot output.
    __stwt(&out[idx],                     o0);  // identity_next
    __stwt(&out[idx +     OUT_STRIDE_V4], o1);  // bloom
    __stwt(&out[idx + 2 * OUT_STRIDE_V4], o2);  // crown
    __stwt(&out[idx + 3 * OUT_STRIDE_V4], o3);  // triad
    __stwt(&out[idx + 4 * OUT_STRIDE_V4], o4);  // spiral
}

extern "C" void kernel_launch(void* const* d_in, const int* in_sizes, int n_in,
                              void* d_out, int out_size) {
    const float4* x = (const float4*)d_in[0];
    float4* out = (float4*)d_out;

    const int threads = 256;
    const int blocks  = TOTAL_V4 / threads;  // 32768
    lattice_kernel<<<blocks, threads>>>(x, out);
}